// round 16
// baseline (speedup 1.0000x reference)
#include <cuda_runtime.h>

// cov = M M^T with m_ik = R(q)_ik * s_k, identical math to the reference.
//
// Memory-bound: 64 B/gaussian, 256 MiB one-pass stream. Measured roof:
// ~35.6us kernel — mixed read/write DRAM turnaround; no pipe >71%
// (DRAM 71%, L2 40%, L1 48%, issue 31%). MLP-raising, persistence, and
// barrier variants all confirmed neutral-or-worse; this is the best design.
//
//  - non-persistent launch (hardware wave packing beats static partition).
//  - warp-autonomous smem staging, one __syncwarp per sub-iteration,
//    no block barriers.
//  - stride-9 STS (odd -> bank-conflict-free), 72 coalesced float4 __stcs
//    per warp-iteration, evict-first (one-pass stream).
//  - 32 regs, 18 KB smem -> 8 blocks/SM.

#define TPB 256
#define EPT 2
#define NW  (TPB / 32)
#define BLK (TPB * EPT)   // 512 elements per block

__device__ __forceinline__ void compute_cov(float4 q, float sx, float sy, float sz,
                                            float* __restrict__ o /* stride-9 row */)
{
    float w = q.x, x = q.y, y = q.z, z = q.w;

    float xx = x * x, yy = y * y, zz = z * z;
    float xy = x * y, xz = x * z, yz = y * z;
    float wx = w * x, wy = w * y, wz = w * z;

    float r00 = 1.0f - 2.0f * (yy + zz);
    float r01 = 2.0f * (xy - wz);
    float r02 = 2.0f * (xz + wy);
    float r10 = 2.0f * (xy + wz);
    float r11 = 1.0f - 2.0f * (xx + zz);
    float r12 = 2.0f * (yz - wx);
    float r20 = 2.0f * (xz - wy);
    float r21 = 2.0f * (yz + wx);
    float r22 = 1.0f - 2.0f * (xx + yy);

    float m00 = r00 * sx, m01 = r01 * sy, m02 = r02 * sz;
    float m10 = r10 * sx, m11 = r11 * sy, m12 = r12 * sz;
    float m20 = r20 * sx, m21 = r21 * sy, m22 = r22 * sz;

    float c00 = m00 * m00 + m01 * m01 + m02 * m02;
    float c01 = m00 * m10 + m01 * m11 + m02 * m12;
    float c02 = m00 * m20 + m01 * m21 + m02 * m22;
    float c11 = m10 * m10 + m11 * m11 + m12 * m12;
    float c12 = m10 * m20 + m11 * m21 + m12 * m22;
    float c22 = m20 * m20 + m21 * m21 + m22 * m22;

    o[0] = c00; o[1] = c01; o[2] = c02;
    o[3] = c01; o[4] = c11; o[5] = c12;
    o[6] = c02; o[7] = c12; o[8] = c22;
}

__global__ __launch_bounds__(TPB) void cov_kernel(
    const float4* __restrict__ quat,   // [N] of (w,x,y,z)
    const float*  __restrict__ scales, // [N*3]
    float*        __restrict__ out,    // [N*9]
    int n)
{
    // per-warp staging, separate buffer per sub-iteration: 18 KB
    __shared__ float s_out[NW][EPT][288];

    const int tid  = threadIdx.x;
    const int w    = tid >> 5;
    const int lane = tid & 31;
    const size_t base = (size_t)blockIdx.x * BLK;

    if (base + BLK <= (size_t)n) {
        // ---------- fast path: no predicates ----------
        const size_t wbase = base + (size_t)w * (32 * EPT);

        #pragma unroll
        for (int k = 0; k < EPT; k++) {
            const size_t e = wbase + k * 32 + lane;

            float4 q = __ldcs(&quat[e]);
            const float* sp = scales + e * 3;
            float sx = __ldcs(sp + 0);
            float sy = __ldcs(sp + 1);
            float sz = __ldcs(sp + 2);

            compute_cov(q, sx, sy, sz, &s_out[w][k][lane * 9]);

            __syncwarp();

            // store-out: 288 floats = 72 float4, base 1152-B aligned
            const float4* sb = reinterpret_cast<const float4*>(&s_out[w][k][0]);
            float4* gb = reinterpret_cast<float4*>(out + (wbase + (size_t)k * 32) * 9);
            __stcs(&gb[lane],      sb[lane]);
            __stcs(&gb[lane + 32], sb[lane + 32]);
            if (lane < 8)
                __stcs(&gb[lane + 64], sb[lane + 64]);
            // no trailing __syncwarp: each k uses a private buffer and each
            // block touches its tile exactly once per launch.
        }
    } else {
        // ---------- tail path: guarded, scalar stores ----------
        const int valid = n - (int)base;
        #pragma unroll
        for (int k = 0; k < EPT; k++) {
            const int e = w * (32 * EPT) + k * 32 + lane;  // block-local
            if (e < valid) {
                const size_t ge = base + e;
                float4 q = __ldcs(&quat[ge]);
                const float* sp = scales + ge * 3;
                float o[9];
                compute_cov(q, __ldcs(sp + 0), __ldcs(sp + 1), __ldcs(sp + 2), o);
                float* g = out + ge * 9;
                #pragma unroll
                for (int j = 0; j < 9; j++) g[j] = o[j];
            }
        }
    }
}

extern "C" void kernel_launch(void* const* d_in, const int* in_sizes, int n_in,
                              void* d_out, int out_size) {
    const float4* quat   = (const float4*)d_in[0]; // quaternions [N,4]
    const float*  scales = (const float*) d_in[1]; // scales [N,3]
    float* out = (float*)d_out;                    // cov [N,3,3]

    int n = in_sizes[0] / 4;
    int grid = (n + BLK - 1) / BLK;
    cov_kernel<<<grid, TPB>>>(quat, scales, out, n);
}

// round 17
// speedup vs baseline: 1.0247x; 1.0247x over previous
#include <cuda_runtime.h>

// cov = M M^T with m_ik = R(q)_ik * s_k, identical math to the reference.
//
// FINAL DESIGN — measured roof. 64 B/gaussian, 268 MB one-pass stream,
// 35.2us kernel = 7.6 TB/s effective; DRAM 72%, L2 41%, L1 49%, issue 31%:
// mixed read/write DRAM-turnaround-limited. Measured-neutral-or-worse:
// MLP raising (R2,R5), persistent grid (R7), block-barrier variants (R1,R2).
//
//  - non-persistent launch (hardware wave packing beats static partition).
//  - warp-autonomous smem staging, one __syncwarp per sub-iteration,
//    no block barriers.
//  - stride-9 STS (odd -> bank-conflict-free), 72 coalesced float4 __stcs
//    per warp-iteration, evict-first (one-pass stream).
//  - 32 regs, 18 KB smem -> 8 blocks/SM.

#define TPB 256
#define EPT 2
#define NW  (TPB / 32)
#define BLK (TPB * EPT)   // 512 elements per block

__device__ __forceinline__ void compute_cov(float4 q, float sx, float sy, float sz,
                                            float* __restrict__ o /* stride-9 row */)
{
    float w = q.x, x = q.y, y = q.z, z = q.w;

    float xx = x * x, yy = y * y, zz = z * z;
    float xy = x * y, xz = x * z, yz = y * z;
    float wx = w * x, wy = w * y, wz = w * z;

    float r00 = 1.0f - 2.0f * (yy + zz);
    float r01 = 2.0f * (xy - wz);
    float r02 = 2.0f * (xz + wy);
    float r10 = 2.0f * (xy + wz);
    float r11 = 1.0f - 2.0f * (xx + zz);
    float r12 = 2.0f * (yz - wx);
    float r20 = 2.0f * (xz - wy);
    float r21 = 2.0f * (yz + wx);
    float r22 = 1.0f - 2.0f * (xx + yy);

    float m00 = r00 * sx, m01 = r01 * sy, m02 = r02 * sz;
    float m10 = r10 * sx, m11 = r11 * sy, m12 = r12 * sz;
    float m20 = r20 * sx, m21 = r21 * sy, m22 = r22 * sz;

    float c00 = m00 * m00 + m01 * m01 + m02 * m02;
    float c01 = m00 * m10 + m01 * m11 + m02 * m12;
    float c02 = m00 * m20 + m01 * m21 + m02 * m22;
    float c11 = m10 * m10 + m11 * m11 + m12 * m12;
    float c12 = m10 * m20 + m11 * m21 + m12 * m22;
    float c22 = m20 * m20 + m21 * m21 + m22 * m22;

    o[0] = c00; o[1] = c01; o[2] = c02;
    o[3] = c01; o[4] = c11; o[5] = c12;
    o[6] = c02; o[7] = c12; o[8] = c22;
}

__global__ __launch_bounds__(TPB) void cov_kernel(
    const float4* __restrict__ quat,   // [N] of (w,x,y,z)
    const float*  __restrict__ scales, // [N*3]
    float*        __restrict__ out,    // [N*9]
    int n)
{
    // per-warp staging, separate buffer per sub-iteration: 18 KB
    __shared__ float s_out[NW][EPT][288];

    const int tid  = threadIdx.x;
    const int w    = tid >> 5;
    const int lane = tid & 31;
    const size_t base = (size_t)blockIdx.x * BLK;

    if (base + BLK <= (size_t)n) {
        // ---------- fast path: no predicates ----------
        const size_t wbase = base + (size_t)w * (32 * EPT);

        #pragma unroll
        for (int k = 0; k < EPT; k++) {
            const size_t e = wbase + k * 32 + lane;

            float4 q = __ldcs(&quat[e]);
            const float* sp = scales + e * 3;
            float sx = __ldcs(sp + 0);
            float sy = __ldcs(sp + 1);
            float sz = __ldcs(sp + 2);

            compute_cov(q, sx, sy, sz, &s_out[w][k][lane * 9]);

            __syncwarp();

            // store-out: 288 floats = 72 float4, base 1152-B aligned
            const float4* sb = reinterpret_cast<const float4*>(&s_out[w][k][0]);
            float4* gb = reinterpret_cast<float4*>(out + (wbase + (size_t)k * 32) * 9);
            __stcs(&gb[lane],      sb[lane]);
            __stcs(&gb[lane + 32], sb[lane + 32]);
            if (lane < 8)
                __stcs(&gb[lane + 64], sb[lane + 64]);
            // no trailing __syncwarp: each k uses a private buffer and each
            // block touches its tile exactly once per launch.
        }
    } else {
        // ---------- tail path: guarded, scalar stores ----------
        const int valid = n - (int)base;
        #pragma unroll
        for (int k = 0; k < EPT; k++) {
            const int e = w * (32 * EPT) + k * 32 + lane;  // block-local
            if (e < valid) {
                const size_t ge = base + e;
                float4 q = __ldcs(&quat[ge]);
                const float* sp = scales + ge * 3;
                float o[9];
                compute_cov(q, __ldcs(sp + 0), __ldcs(sp + 1), __ldcs(sp + 2), o);
                float* g = out + ge * 9;
                #pragma unroll
                for (int j = 0; j < 9; j++) g[j] = o[j];
            }
        }
    }
}

extern "C" void kernel_launch(void* const* d_in, const int* in_sizes, int n_in,
                              void* d_out, int out_size) {
    const float4* quat   = (const float4*)d_in[0]; // quaternions [N,4]
    const float*  scales = (const float*) d_in[1]; // scales [N,3]
    float* out = (float*)d_out;                    // cov [N,3,3]

    int n = in_sizes[0] / 4;
    int grid = (n + BLK - 1) / BLK;
    cov_kernel<<<grid, TPB>>>(quat, scales, out, n);
}